// round 2
// baseline (speedup 1.0000x reference)
#include <cuda_runtime.h>

#define HH 64
#define G4 256        // 4*H
#define SEQ 512
#define BT 32         // batch elems per CTA
#define NTHREADS 256
#define CHUNK 64
#define XSTRIDE 65    // padded to avoid bank conflicts on sx reads

// shared memory float offsets
#define OFF_W1   0
#define OFF_W2I  16384
#define OFF_W2H  32768
#define OFF_WIH1 49152
#define OFF_B1   49408
#define OFF_B2   49664
#define OFF_H1   49920
#define OFF_H2   51968
#define OFF_X    54016
#define SMEM_FLOATS (54016 + BT*XSTRIDE)   // 56096
#define SMEM_BYTES  (SMEM_FLOATS*4)        // 224384 bytes

__device__ __forceinline__ float sigf(float x) {
    return __fdividef(1.f, 1.f + __expf(-x));
}
__device__ __forceinline__ float tanh_fast(float x) {
    return __fdividef(2.f, 1.f + __expf(-2.f*x)) - 1.f;
}

// z[8] float4 accumulators: z[gt*2+h] covers gate gt, units h*4..h*4+3 of this
// thread's 8-unit slice. W layout: [k][j] (j = gate*64 + unit), warp-broadcast reads.
__device__ __forceinline__ void matvec_acc(float4 z[8], const float* __restrict__ W,
                                           const float* __restrict__ hv,
                                           int e, int jb) {
    #pragma unroll 4
    for (int k = 0; k < HH; ++k) {
        float hk = hv[k*BT + e];
        #pragma unroll
        for (int gt = 0; gt < 4; ++gt) {
            const float4* wp = (const float4*)(W + k*G4 + gt*HH + jb);
            float4 w0 = wp[0], w1 = wp[1];
            float4 a0 = z[gt*2], a1 = z[gt*2+1];
            a0.x += w0.x*hk; a0.y += w0.y*hk; a0.z += w0.z*hk; a0.w += w0.w*hk;
            a1.x += w1.x*hk; a1.y += w1.y*hk; a1.z += w1.z*hk; a1.w += w1.w*hk;
            z[gt*2] = a0; z[gt*2+1] = a1;
        }
    }
}

#define ACT1(C, HN, XI, XF, XG, XO) { \
    float iv = sigf(XI), fv = sigf(XF), gv = tanh_fast(XG), ov = sigf(XO); \
    (C) = fv*(C) + iv*gv; (HN) = ov*tanh_fast(C); }

__device__ __forceinline__ void lstm_act(const float4 z[8], float c[8], float hn[8]) {
    #pragma unroll
    for (int h = 0; h < 2; ++h) {
        float4 zi = z[0+h], zf = z[2+h], zg = z[4+h], zo = z[6+h];
        ACT1(c[h*4+0], hn[h*4+0], zi.x, zf.x, zg.x, zo.x);
        ACT1(c[h*4+1], hn[h*4+1], zi.y, zf.y, zg.y, zo.y);
        ACT1(c[h*4+2], hn[h*4+2], zi.z, zf.z, zg.z, zo.z);
        ACT1(c[h*4+3], hn[h*4+3], zi.w, zf.w, zg.w, zo.w);
    }
}

__global__ __launch_bounds__(NTHREADS, 1)
void lstm_fused(const float* __restrict__ x,
                const float* __restrict__ Wih1,
                const float* __restrict__ Whh1,
                const float* __restrict__ bih1,
                const float* __restrict__ bhh1,
                const float* __restrict__ Wih2,
                const float* __restrict__ Whh2,
                const float* __restrict__ bih2,
                const float* __restrict__ bhh2,
                const float* __restrict__ Wd1,
                const float* __restrict__ bd1,
                const float* __restrict__ Wd2,
                const float* __restrict__ bd2,
                float* __restrict__ out)
{
    extern __shared__ float sm[];
    float* sW1  = sm + OFF_W1;    // W_hh1^T [k][j]
    float* sW2i = sm + OFF_W2I;   // W_ih2^T [k][j]
    float* sW2h = sm + OFF_W2H;   // W_hh2^T [k][j]
    float* swih = sm + OFF_WIH1;  // W_ih1 column (F=1) [j]
    float* sb1  = sm + OFF_B1;    // b_ih1+b_hh1
    float* sb2  = sm + OFF_B2;    // b_ih2+b_hh2
    float* sh1  = sm + OFF_H1;    // h1 state [k][e]
    float* sh2  = sm + OFF_H2;    // h2 state [k][e]
    float* sx   = sm + OFF_X;     // x chunk [e][sl] stride 65 (reused as smid)

    const int tid = threadIdx.x;
    const int e  = tid & 31;      // batch elem within tile == lane
    const int g  = tid >> 5;      // unit group (warp id)
    const int jb = g * 8;         // unit base for this thread
    const int b0 = blockIdx.x * BT;

    // Transpose recurrent weights into SMEM: s[k*256+j] = W[j*64+k]
    for (int idx = tid; idx < HH*G4; idx += NTHREADS) {
        int k = idx >> 8, j = idx & 255;
        sW1[idx]  = Whh1[j*HH + k];
        sW2i[idx] = Wih2[j*HH + k];
        sW2h[idx] = Whh2[j*HH + k];
    }
    for (int j = tid; j < G4; j += NTHREADS) {
        swih[j] = Wih1[j];
        sb1[j]  = bih1[j] + bhh1[j];
        sb2[j]  = bih2[j] + bhh2[j];
    }
    for (int i = tid; i < BT*HH; i += NTHREADS) { sh1[i] = 0.f; sh2[i] = 0.f; }

    float c1[8], c2[8];
    #pragma unroll
    for (int q = 0; q < 8; ++q) { c1[q] = 0.f; c2[q] = 0.f; }

    float4 z[8];

    for (int s = 0; s < SEQ; ++s) {
        const int sl = s & (CHUNK-1);
        __syncthreads();   // protects sh1/sh2/sx reuse across iterations
        if (sl == 0) {
            // stage next 64 timesteps of x for the 32 elems (coalesced gmem reads)
            for (int i = tid; i < BT*CHUNK; i += NTHREADS) {
                int e2 = i >> 6, q = i & 63;
                sx[e2*XSTRIDE + q] = x[(size_t)(b0+e2)*SEQ + s + q];
            }
            __syncthreads();
        }
        float xv = sx[e*XSTRIDE + sl];

        // ---- layer 1: z = (b_ih1+b_hh1) + x_t * w_ih1 + W_hh1 @ h1_prev ----
        #pragma unroll
        for (int gt = 0; gt < 4; ++gt) {
            const float4* bp = (const float4*)(sb1  + gt*HH + jb);
            const float4* wp = (const float4*)(swih + gt*HH + jb);
            #pragma unroll
            for (int h = 0; h < 2; ++h) {
                float4 b = bp[h], w = wp[h];
                z[gt*2+h] = make_float4(b.x + xv*w.x, b.y + xv*w.y,
                                        b.z + xv*w.z, b.w + xv*w.w);
            }
        }
        matvec_acc(z, sW1, sh1, e, jb);

        float h1n[8];
        lstm_act(z, c1, h1n);

        // ---- layer 2 part A: z = (b_ih2+b_hh2) + W_hh2 @ h2_prev ----
        #pragma unroll
        for (int gt = 0; gt < 4; ++gt) {
            const float4* bp = (const float4*)(sb2 + gt*HH + jb);
            z[gt*2]   = bp[0];
            z[gt*2+1] = bp[1];
        }
        matvec_acc(z, sW2h, sh2, e, jb);

        __syncthreads();   // all reads of sh1_prev / sh2_prev done
        #pragma unroll
        for (int q = 0; q < 8; ++q) sh1[(jb+q)*BT + e] = h1n[q];
        __syncthreads();   // new h1 visible

        // ---- layer 2 part B: z += W_ih2 @ h1_new ----
        matvec_acc(z, sW2i, sh1, e, jb);

        float h2n[8];
        lstm_act(z, c2, h2n);
        #pragma unroll
        for (int q = 0; q < 8; ++q) sh2[(jb+q)*BT + e] = h2n[q];
        // next top-of-loop barrier protects these writes
    }

    __syncthreads();

    // ---- dense head: relu(h2 @ Wd1^T + bd1) @ Wd2^T + bd2 ----
    float* smid = sx;   // reuse as [m][e], 32*32 floats
    #pragma unroll
    for (int mm = 0; mm < 4; ++mm) {
        int m = g*4 + mm;
        float acc = bd1[m];
        #pragma unroll 8
        for (int k = 0; k < HH; ++k)
            acc += sh2[k*BT + e] * Wd1[m*HH + k];
        smid[m*BT + e] = fmaxf(acc, 0.f);
    }
    __syncthreads();
    if (g < 6) {
        #pragma unroll
        for (int oo = 0; oo < 4; ++oo) {
            int o = g*4 + oo;
            float acc = bd2[o];
            #pragma unroll
            for (int m = 0; m < 32; ++m)
                acc += smid[m*BT + e] * Wd2[o*32 + m];
            out[(b0+e)*24 + o] = acc;
        }
    }
}

extern "C" void kernel_launch(void* const* d_in, const int* in_sizes, int n_in,
                              void* d_out, int out_size) {
    (void)in_sizes; (void)n_in; (void)out_size;
    const float* x    = (const float*)d_in[0];
    const float* Wih1 = (const float*)d_in[1];
    const float* Whh1 = (const float*)d_in[2];
    const float* bih1 = (const float*)d_in[3];
    const float* bhh1 = (const float*)d_in[4];
    const float* Wih2 = (const float*)d_in[5];
    const float* Whh2 = (const float*)d_in[6];
    const float* bih2 = (const float*)d_in[7];
    const float* bhh2 = (const float*)d_in[8];
    const float* Wd1  = (const float*)d_in[9];
    const float* bd1  = (const float*)d_in[10];
    const float* Wd2  = (const float*)d_in[11];
    const float* bd2  = (const float*)d_in[12];
    float* out = (float*)d_out;

    cudaFuncSetAttribute(lstm_fused, cudaFuncAttributeMaxDynamicSharedMemorySize,
                         SMEM_BYTES);
    lstm_fused<<<4096/BT, NTHREADS, SMEM_BYTES>>>(
        x, Wih1, Whh1, bih1, bhh1, Wih2, Whh2, bih2, bhh2,
        Wd1, bd1, Wd2, bd2, out);
}

// round 7
// speedup vs baseline: 5.3169x; 5.3169x over previous
#include <cuda_runtime.h>
#include <cuda_fp16.h>
#include <cstdint>

#define NTHREADS 256
#define SEQ 512
#define BT 32
#define XCH 32

// ---- SMEM byte offsets ----
#define OFF_H1HI 0          // h1 hi fp16 [32][64], swizzled, 4096 B
#define OFF_H1LO 4096
#define OFF_H2HI 8192
#define OFF_H2LO 12288
#define OFF_XAUG 16384      // x aug tile [32 rows][stride 48 B] fp16 (cols0,1 = x hi,lo)
#define OFF_SX   17920      // x chunk fp32 [32][33]
#define OFF_W1   22528      // Whh1 staging f16 [256][64]
#define OFF_W2H  55296      // Whh2
#define OFF_W2I  88064      // Wih2
#define OFF_WAUG 120832     // aug B staging [256][stride 32 B] (cols0,1 = wih1)
#define SMEM_BYTES 129024

static __device__ __forceinline__ uint32_t smem_u32(const void* p) {
    uint32_t a;
    asm("{ .reg .u64 t; cvta.to.shared.u64 t, %1; cvt.u32.u64 %0, t; }" : "=r"(a) : "l"(p));
    return a;
}

static __device__ __forceinline__ void ldsm4(uint32_t a[4], uint32_t addr) {
    asm volatile("ldmatrix.sync.aligned.m8n8.x4.shared.b16 {%0,%1,%2,%3}, [%4];"
                 : "=r"(a[0]), "=r"(a[1]), "=r"(a[2]), "=r"(a[3]) : "r"(addr));
}
static __device__ __forceinline__ void ldsm2(uint32_t a[2], uint32_t addr) {
    asm volatile("ldmatrix.sync.aligned.m8n8.x2.shared.b16 {%0,%1}, [%2];"
                 : "=r"(a[0]), "=r"(a[1]) : "r"(addr));
}
// d += A*B  (in-place accumulate)
static __device__ __forceinline__ void mma_acc(float d[4], const uint32_t a[4],
                                               const uint32_t b[2]) {
    asm volatile("mma.sync.aligned.m16n8k16.row.col.f32.f16.f16.f32 "
                 "{%0,%1,%2,%3}, {%4,%5,%6,%7}, {%8,%9}, {%0,%1,%2,%3};"
                 : "+f"(d[0]), "+f"(d[1]), "+f"(d[2]), "+f"(d[3])
                 : "r"(a[0]), "r"(a[1]), "r"(a[2]), "r"(a[3]), "r"(b[0]), "r"(b[1]));
}
// d = A*B + {c0,c1,c0,c1}   (bias seed: bias depends only on the N column)
static __device__ __forceinline__ void mma_init(float d[4], const uint32_t a[4],
                                                const uint32_t b[2], float c0, float c1) {
    asm volatile("mma.sync.aligned.m16n8k16.row.col.f32.f16.f16.f32 "
                 "{%0,%1,%2,%3}, {%4,%5,%6,%7}, {%8,%9}, {%10,%11,%10,%11};"
                 : "=f"(d[0]), "=f"(d[1]), "=f"(d[2]), "=f"(d[3])
                 : "r"(a[0]), "r"(a[1]), "r"(a[2]), "r"(a[3]), "r"(b[0]), "r"(b[1]),
                   "f"(c0), "f"(c1));
}

static __device__ __forceinline__ float sigf(float x) {
    return __fdividef(1.f, 1.f + __expf(-x));
}
static __device__ __forceinline__ float tanhfast(float x) {
    return __fdividef(2.f, 1.f + __expf(-2.f * x)) - 1.f;
}

__global__ __launch_bounds__(NTHREADS, 1)
void lstm_hmma(const float* __restrict__ x,
               const float* __restrict__ Wih1, const float* __restrict__ Whh1,
               const float* __restrict__ bih1, const float* __restrict__ bhh1,
               const float* __restrict__ Wih2, const float* __restrict__ Whh2,
               const float* __restrict__ bih2, const float* __restrict__ bhh2,
               const float* __restrict__ Wd1,  const float* __restrict__ bd1,
               const float* __restrict__ Wd2,  const float* __restrict__ bd2,
               float* __restrict__ out)
{
    extern __shared__ char sm[];
    const uint32_t sb = smem_u32(sm);
    const int tid = threadIdx.x;
    const int w = tid >> 5, l = tid & 31;
    const int b0 = blockIdx.x * BT;

    // ---- stage weights to SMEM fp16 ----
    for (int i = tid; i < 256 * 64; i += NTHREADS) {
        ((__half*)(sm + OFF_W1 ))[i] = __float2half(Whh1[i]);
        ((__half*)(sm + OFF_W2H))[i] = __float2half(Whh2[i]);
        ((__half*)(sm + OFF_W2I))[i] = __float2half(Wih2[i]);
    }
    for (int i = tid; i < 4096; i += NTHREADS) ((__half*)(sm + OFF_WAUG))[i] = __ushort_as_half(0);
    for (int i = tid; i < 16384 / 4; i += NTHREADS) ((uint32_t*)(sm + OFF_H1HI))[i] = 0;  // zero h tiles
    for (int i = tid; i < 1536 / 4; i += NTHREADS)  ((uint32_t*)(sm + OFF_XAUG))[i] = 0;
    __syncthreads();
    for (int j = tid; j < 256; j += NTHREADS) {
        __half wv = __float2half(Wih1[j]);
        ((__half*)(sm + OFF_WAUG))[j * 16 + 0] = wv;   // multiplies x_hi
        ((__half*)(sm + OFF_WAUG))[j * 16 + 1] = wv;   // multiplies x_lo
    }
    __syncthreads();

    // ---- load static B fragments into registers ----
    // warp w owns units u in [8w, 8w+8) for all 4 gates; gate g -> N-rows g*64+8w..+8
    uint32_t Bw1[4][4][2], Bw2h[4][4][2], Bw2i[4][4][2], Baug[4][2];
    float b1c[4][2], b2c[4][2];
    #pragma unroll
    for (int g = 0; g < 4; ++g) {
        const int j0 = g * 64 + w * 8;
        #pragma unroll
        for (int p = 0; p < 2; ++p) {
            uint32_t off = (uint32_t)((j0 + (l & 7)) * 128 + p * 64 + (l >> 3) * 16);
            uint32_t t[4];
            ldsm4(t, sb + OFF_W1 + off);
            Bw1[g][2*p][0] = t[0]; Bw1[g][2*p][1] = t[1];
            Bw1[g][2*p+1][0] = t[2]; Bw1[g][2*p+1][1] = t[3];
            ldsm4(t, sb + OFF_W2H + off);
            Bw2h[g][2*p][0] = t[0]; Bw2h[g][2*p][1] = t[1];
            Bw2h[g][2*p+1][0] = t[2]; Bw2h[g][2*p+1][1] = t[3];
            ldsm4(t, sb + OFF_W2I + off);
            Bw2i[g][2*p][0] = t[0]; Bw2i[g][2*p][1] = t[1];
            Bw2i[g][2*p+1][0] = t[2]; Bw2i[g][2*p+1][1] = t[3];
        }
        ldsm2(Baug[g], sb + OFF_WAUG + (uint32_t)((j0 + (l & 7)) * 32 + ((l >> 3) & 1) * 16));
        #pragma unroll
        for (int j = 0; j < 2; ++j) {
            int idx = j0 + (l & 3) * 2 + j;
            b1c[g][j] = bih1[idx] + bhh1[idx];
            b2c[g][j] = bih2[idx] + bhh2[idx];
        }
    }

    // per-lane ldmatrix address components for the h tiles (rows stride 128 B, XOR-16B swizzle)
    const int mm = l >> 3;
    const int rbase = ((mm & 1) << 3) + (l & 7);       // row within 16-row Mtile
    const uint32_t khalf = (uint32_t)((mm >> 1) << 4); // 16-B k-half select
    const uint32_t swz = (uint32_t)((rbase & 7) << 4);
    // xaug addresses (rows stride 48 B, no swizzle)
    uint32_t xaddr[2];
    #pragma unroll
    for (int m = 0; m < 2; ++m)
        xaddr[m] = sb + OFF_XAUG + (uint32_t)((m * 16 + rbase) * 48) + khalf;

    const uint32_t hb1[2] = { sb + OFF_H1HI, sb + OFF_H1LO };
    const uint32_t hb2[2] = { sb + OFF_H2HI, sb + OFF_H2LO };

    // epilogue store addresses: lane holds rows {m*16 + l/4, +8}, units u0=(8w+(l&3)*2)
    const int erow = l >> 2;
    const int ucol = w * 16 + (l & 3) * 4;  // byte offset of unit pair within row

    float c1s[8], c2s[8];
    #pragma unroll
    for (int i = 0; i < 8; ++i) { c1s[i] = 0.f; c2s[i] = 0.f; }

    float* sx = (float*)(sm + OFF_SX);

    for (int s = 0; s < SEQ; ++s) {
        const int sl = s & (XCH - 1);
        if (sl == 0) {
            for (int i = tid; i < BT * XCH; i += NTHREADS) {
                int r2 = i >> 5, q = i & 31;
                sx[r2 * 33 + q] = x[(size_t)(b0 + r2) * SEQ + s + q];
            }
            __syncthreads();
        }
        if (tid < BT) {   // write x hi/lo into aug tile
            float xv = sx[tid * 33 + sl];
            __half hi = __float2half_rn(xv);
            __half lo = __float2half_rn(xv - __half2float(hi));
            *(__half*)(sm + OFF_XAUG + tid * 48)     = hi;
            *(__half*)(sm + OFF_XAUG + tid * 48 + 2) = lo;
        }
        __syncthreads();   // S1: xaug + prev h2 visible

        // ---- Z1 = bias1 + x*wih1 + h1_prev @ Whh1^T ----
        float zz[2][4][4];
        {
            uint32_t Aau[2][4];
            ldsm4(Aau[0], xaddr[0]);
            ldsm4(Aau[1], xaddr[1]);
            #pragma unroll
            for (int m = 0; m < 2; ++m)
                #pragma unroll
                for (int g = 0; g < 4; ++g)
                    mma_init(zz[m][g], Aau[m], Baug[g], b1c[g][0], b1c[g][1]);
        }
        #pragma unroll
        for (int pp = 0; pp < 2; ++pp) {
            #pragma unroll
            for (int kt = 0; kt < 4; ++kt) {
                #pragma unroll
                for (int m = 0; m < 2; ++m) {
                    uint32_t a[4];
                    uint32_t rowb = (uint32_t)((m * 16 + rbase) * 128);
                    ldsm4(a, hb1[pp] + rowb + (((uint32_t)kt * 32 + khalf) ^ swz));
                    #pragma unroll
                    for (int g = 0; g < 4; ++g)
                        mma_acc(zz[m][g], a, Bw1[g][kt]);
                }
            }
        }
        __syncthreads();   // S2: all h1_prev reads done

        // ---- epilogue 1 -> h1_new (hi/lo to SMEM) ----
        #pragma unroll
        for (int m = 0; m < 2; ++m) {
            float hv[4];
            #pragma unroll
            for (int slot = 0; slot < 4; ++slot) {
                float iv = sigf(zz[m][0][slot]);
                float fv = sigf(zz[m][1][slot]);
                float gv = tanhfast(zz[m][2][slot]);
                float ov = sigf(zz[m][3][slot]);
                float cc = fv * c1s[m * 4 + slot] + iv * gv;
                c1s[m * 4 + slot] = cc;
                hv[slot] = ov * tanhfast(cc);
            }
            #pragma unroll
            for (int rr = 0; rr < 2; ++rr) {
                int r = m * 16 + erow + rr * 8;
                __half h0 = __float2half_rn(hv[rr*2]);
                __half h1 = __float2half_rn(hv[rr*2+1]);
                __half l0 = __float2half_rn(hv[rr*2]   - __half2float(h0));
                __half l1 = __float2half_rn(hv[rr*2+1] - __half2float(h1));
                uint32_t off = (uint32_t)(r * 128) + (((uint32_t)ucol) ^ ((uint32_t)(r & 7) << 4));
                *(__half2*)(sm + OFF_H1HI + off) = __halves2half2(h0, h1);
                *(__half2*)(sm + OFF_H1LO + off) = __halves2half2(l0, l1);
            }
        }
        __syncthreads();   // S3: h1_new visible

        // ---- Z2 = bias2 + h2_prev @ Whh2^T + h1_new @ Wih2^T ----
        #pragma unroll
        for (int pp = 0; pp < 4; ++pp) {
            const uint32_t hbase = (pp < 2) ? hb2[pp] : hb1[pp - 2];
            #pragma unroll
            for (int kt = 0; kt < 4; ++kt) {
                #pragma unroll
                for (int m = 0; m < 2; ++m) {
                    uint32_t a[4];
                    uint32_t rowb = (uint32_t)((m * 16 + rbase) * 128);
                    ldsm4(a, hbase + rowb + (((uint32_t)kt * 32 + khalf) ^ swz));
                    #pragma unroll
                    for (int g = 0; g < 4; ++g) {
                        const uint32_t* bf = (pp < 2) ? Bw2h[g][kt] : Bw2i[g][kt];
                        if (pp == 0 && kt == 0)
                            mma_init(zz[m][g], a, bf, b2c[g][0], b2c[g][1]);
                        else
                            mma_acc(zz[m][g], a, bf);
                    }
                }
            }
        }
        __syncthreads();   // S4: all h2_prev / h1_new reads done

        // ---- epilogue 2 -> h2_new ----
        #pragma unroll
        for (int m = 0; m < 2; ++m) {
            float hv[4];
            #pragma unroll
            for (int slot = 0; slot < 4; ++slot) {
                float iv = sigf(zz[m][0][slot]);
                float fv = sigf(zz[m][1][slot]);
                float gv = tanhfast(zz[m][2][slot]);
                float ov = sigf(zz[m][3][slot]);
                float cc = fv * c2s[m * 4 + slot] + iv * gv;
                c2s[m * 4 + slot] = cc;
                hv[slot] = ov * tanhfast(cc);
            }
            #pragma unroll
            for (int rr = 0; rr < 2; ++rr) {
                int r = m * 16 + erow + rr * 8;
                __half h0 = __float2half_rn(hv[rr*2]);
                __half h1 = __float2half_rn(hv[rr*2+1]);
                __half l0 = __float2half_rn(hv[rr*2]   - __half2float(h0));
                __half l1 = __float2half_rn(hv[rr*2+1] - __half2float(h1));
                uint32_t off = (uint32_t)(r * 128) + (((uint32_t)ucol) ^ ((uint32_t)(r & 7) << 4));
                *(__half2*)(sm + OFF_H2HI + off) = __halves2half2(h0, h1);
                *(__half2*)(sm + OFF_H2LO + off) = __halves2half2(l0, l1);
            }
        }
        // next S1 barrier protects these writes
    }

    __syncthreads();

    // ---- dense head: relu(h2 @ Wd1^T + bd1) @ Wd2^T + bd2 ----
    if (tid < BT) {
        float hb[64];
        #pragma unroll 8
        for (int k = 0; k < 64; ++k) {
            uint32_t off = (uint32_t)(tid * 128) +
                           (((uint32_t)(k * 2)) ^ ((uint32_t)(tid & 7) << 4));
            float hi = __half2float(*(const __half*)(sm + OFF_H2HI + off));
            float lo = __half2float(*(const __half*)(sm + OFF_H2LO + off));
            hb[k] = hi + lo;
        }
        float mid[32];
        #pragma unroll 4
        for (int m = 0; m < 32; ++m) {
            float acc = bd1[m];
            #pragma unroll 8
            for (int k = 0; k < 64; ++k) acc += hb[k] * Wd1[m * 64 + k];
            mid[m] = fmaxf(acc, 0.f);
        }
        #pragma unroll 4
        for (int o = 0; o < 24; ++o) {
            float acc = bd2[o];
            #pragma unroll
            for (int m = 0; m < 32; ++m) acc += mid[m] * Wd2[o * 32 + m];
            out[(size_t)(b0 + tid) * 24 + o] = acc;
        }
    }
}

extern "C" void kernel_launch(void* const* d_in, const int* in_sizes, int n_in,
                              void* d_out, int out_size) {
    (void)in_sizes; (void)n_in; (void)out_size;
    const float* x    = (const float*)d_in[0];
    const float* Wih1 = (const float*)d_in[1];
    const float* Whh1 = (const float*)d_in[2];
    const float* bih1 = (const float*)d_in[3];
    const float* bhh1 = (const float*)d_in[4];
    const float* Wih2 = (const float*)d_in[5];
    const float* Whh2 = (const float*)d_in[6];
    const float* bih2 = (const float*)d_in[7];
    const float* bhh2 = (const float*)d_in[8];
    const float* Wd1  = (const float*)d_in[9];
    const float* bd1  = (const float*)d_in[10];
    const float* Wd2  = (const float*)d_in[11];
    const float* bd2  = (const float*)d_in[12];
    float* out = (float*)d_out;

    cudaFuncSetAttribute(lstm_hmma, cudaFuncAttributeMaxDynamicSharedMemorySize, SMEM_BYTES);
    lstm_hmma<<<4096 / BT, NTHREADS, SMEM_BYTES>>>(
        x, Wih1, Whh1, bih1, bhh1, Wih2, Whh2, bih2, bhh2,
        Wd1, bd1, Wd2, bd2, out);
}